// round 2
// baseline (speedup 1.0000x reference)
#include <cuda_runtime.h>
#include <cuda_fp16.h>
#include <cstdint>

#define MDIM 4096
#define NDIM 4096
#define KDIM 4096

#define BM 128
#define BN 128
#define BK 32
#define APAD 8
#define BPAD 8

// Scratch (allocation-free rule: __device__ globals)
__device__ __half g_x16[(size_t)MDIM * KDIM];
__device__ __half g_w16[(size_t)KDIM * NDIM];

__device__ __forceinline__ uint32_t smem_u32(const void* p) {
    return (uint32_t)__cvta_generic_to_shared(p);
}

// ---------------------------------------------------------------------------
// Kernel 1: dequantize packed 4-bit -> fp16 W[k][n]
// packed layout: packed[i, n] holds k = i*8 + j in nibble j (j = 0..7)
// group g = (i*8)/128 = i/16 (constant over the 8 nibbles)
// ---------------------------------------------------------------------------
__global__ void k_dequant(const int* __restrict__ packed,
                          const float* __restrict__ scales,
                          const float* __restrict__ zeros) {
    int idx = blockIdx.x * blockDim.x + threadIdx.x;   // over (K/8)*N = 2M
    int n = idx & (NDIM - 1);
    int i = idx >> 12;                                  // / 4096
    int g = i >> 4;
    float s = __ldg(&scales[g * NDIM + n]);
    float z = __ldg(&zeros[g * NDIM + n]);
    int p = __ldg(&packed[idx]);
#pragma unroll
    for (int j = 0; j < 8; j++) {
        int w = (p >> (4 * j)) & 15;
        g_w16[(size_t)(i * 8 + j) * NDIM + n] = __float2half(((float)w - z) * s);
    }
}

// ---------------------------------------------------------------------------
// Kernel 2: x fp32 -> fp16
// ---------------------------------------------------------------------------
__global__ void k_cvt_x(const float* __restrict__ x) {
    int idx = blockIdx.x * blockDim.x + threadIdx.x;   // over 16M/4
    float4 v = ((const float4*)x)[idx];
    __half2 h0 = __floats2half2_rn(v.x, v.y);
    __half2 h1 = __floats2half2_rn(v.z, v.w);
    ((__half2*)g_x16)[idx * 2 + 0] = h0;
    ((__half2*)g_x16)[idx * 2 + 1] = h1;
}

// ---------------------------------------------------------------------------
// Kernel 3: fp16 GEMM, fp32 accumulate, + bias
// 128x128x32 block tile, 256 threads (8 warps, 4x2), warp tile 32x64,
// mma.sync.m16n8k16, cp.async double buffer.
// ---------------------------------------------------------------------------
__global__ void __launch_bounds__(256, 2)
k_gemm(const float* __restrict__ bias, float* __restrict__ C) {
    __shared__ __half As[2][BM][BK + APAD];
    __shared__ __half Bs[2][BK][BN + BPAD];

    const int tid  = threadIdx.x;
    const int warp = tid >> 5;
    const int lane = tid & 31;
    const int wm = warp & 3;    // 4 warps along M
    const int wn = warp >> 2;   // 2 warps along N
    const int bm = blockIdx.y * BM;
    const int bn = blockIdx.x * BN;

    float acc[2][8][4];
#pragma unroll
    for (int mt = 0; mt < 2; mt++)
#pragma unroll
        for (int nt = 0; nt < 8; nt++)
#pragma unroll
            for (int r = 0; r < 4; r++) acc[mt][nt][r] = 0.0f;

    const __half* Aglob = g_x16;
    const __half* Bglob = g_w16;

    // tile loader: A chunk c in [0,512): row=c>>2, col8=c&3 ; B: row=c>>4, col8=c&15
#define LOAD_TILES(KT_, BUF_)                                                     \
    do {                                                                          \
        int k0_ = (KT_) * BK;                                                     \
        _Pragma("unroll")                                                         \
        for (int i_ = 0; i_ < 2; i_++) {                                          \
            int c_ = tid + i_ * 256;                                              \
            int ar_ = c_ >> 2, ac_ = (c_ & 3) * 8;                                \
            const __half* gA_ = Aglob + (size_t)(bm + ar_) * KDIM + k0_ + ac_;    \
            uint32_t sA_ = smem_u32(&As[BUF_][ar_][ac_]);                         \
            asm volatile("cp.async.cg.shared.global [%0], [%1], 16;\n"            \
                         :: "r"(sA_), "l"(gA_) : "memory");                       \
            int br_ = c_ >> 4, bc_ = (c_ & 15) * 8;                               \
            const __half* gB_ = Bglob + (size_t)(k0_ + br_) * NDIM + bn + bc_;    \
            uint32_t sB_ = smem_u32(&Bs[BUF_][br_][bc_]);                         \
            asm volatile("cp.async.cg.shared.global [%0], [%1], 16;\n"            \
                         :: "r"(sB_), "l"(gB_) : "memory");                       \
        }                                                                         \
        asm volatile("cp.async.commit_group;\n" ::: "memory");                    \
    } while (0)

    LOAD_TILES(0, 0);

    const int KT = KDIM / BK;   // 128
    for (int kt = 0; kt < KT; kt++) {
        int buf = kt & 1;
        if (kt + 1 < KT) {
            LOAD_TILES(kt + 1, buf ^ 1);
            asm volatile("cp.async.wait_group 1;\n" ::: "memory");
        } else {
            asm volatile("cp.async.wait_group 0;\n" ::: "memory");
        }
        __syncthreads();

#pragma unroll
        for (int ks = 0; ks < 2; ks++) {            // two k16 steps per BK=32
            int k0 = ks * 16;
            // A fragments: 2 x (16x16)
            uint32_t a[2][4];
#pragma unroll
            for (int mt = 0; mt < 2; mt++) {
                int row = wm * 32 + mt * 16 + (lane & 15);
                int col = k0 + (lane >> 4) * 8;
                uint32_t addr = smem_u32(&As[buf][row][col]);
                asm volatile(
                    "ldmatrix.sync.aligned.m8n8.x4.shared.b16 {%0,%1,%2,%3}, [%4];\n"
                    : "=r"(a[mt][0]), "=r"(a[mt][1]), "=r"(a[mt][2]), "=r"(a[mt][3])
                    : "r"(addr));
            }
            // B fragments: 8 x (16x8), loaded as 4 x ldmatrix.x4.trans (k16 x n16)
            uint32_t b[8][2];
#pragma unroll
            for (int nq = 0; nq < 4; nq++) {
                int row = k0 + (lane & 15);
                int col = wn * 64 + nq * 16 + (lane >> 4) * 8;
                uint32_t addr = smem_u32(&Bs[buf][row][col]);
                asm volatile(
                    "ldmatrix.sync.aligned.m8n8.x4.trans.shared.b16 {%0,%1,%2,%3}, [%4];\n"
                    : "=r"(b[nq * 2][0]), "=r"(b[nq * 2][1]),
                      "=r"(b[nq * 2 + 1][0]), "=r"(b[nq * 2 + 1][1])
                    : "r"(addr));
            }
#pragma unroll
            for (int mt = 0; mt < 2; mt++) {
#pragma unroll
                for (int nt = 0; nt < 8; nt++) {
                    asm volatile(
                        "mma.sync.aligned.m16n8k16.row.col.f32.f16.f16.f32 "
                        "{%0,%1,%2,%3}, {%4,%5,%6,%7}, {%8,%9}, {%0,%1,%2,%3};\n"
                        : "+f"(acc[mt][nt][0]), "+f"(acc[mt][nt][1]),
                          "+f"(acc[mt][nt][2]), "+f"(acc[mt][nt][3])
                        : "r"(a[mt][0]), "r"(a[mt][1]), "r"(a[mt][2]), "r"(a[mt][3]),
                          "r"(b[nt][0]), "r"(b[nt][1]));
                }
            }
        }
        __syncthreads();
    }

    // epilogue: c0,c1 -> (row = lane/4, col = 2*(lane%4) {,+1}); c2,c3 -> row+8
#pragma unroll
    for (int mt = 0; mt < 2; mt++) {
        int row0 = bm + wm * 32 + mt * 16 + (lane >> 2);
#pragma unroll
        for (int nt = 0; nt < 8; nt++) {
            int col = bn + wn * 64 + nt * 8 + (lane & 3) * 2;
            float b0 = __ldg(&bias[col]);
            float b1 = __ldg(&bias[col + 1]);
            float2 v0 = make_float2(acc[mt][nt][0] + b0, acc[mt][nt][1] + b1);
            float2 v1 = make_float2(acc[mt][nt][2] + b0, acc[mt][nt][3] + b1);
            *(float2*)&C[(size_t)row0 * NDIM + col] = v0;
            *(float2*)&C[(size_t)(row0 + 8) * NDIM + col] = v1;
        }
    }
}

// ---------------------------------------------------------------------------
// Launch: inputs in metadata order: x, W_q_packed, scales, zeros, bias
// ---------------------------------------------------------------------------
extern "C" void kernel_launch(void* const* d_in, const int* in_sizes, int n_in,
                              void* d_out, int out_size) {
    const float* x      = (const float*)d_in[0];
    const int*   wq     = (const int*)d_in[1];
    const float* scales = (const float*)d_in[2];
    const float* zeros  = (const float*)d_in[3];
    const float* bias   = (const float*)d_in[4];
    float* out = (float*)d_out;

    {   // dequant W: (K/8)*N = 2M threads
        int total = (KDIM / 8) * NDIM;
        k_dequant<<<total / 256, 256>>>(wq, scales, zeros);
    }
    {   // convert x: 16M elems, 4 per thread
        int total = (MDIM * KDIM) / 4;
        k_cvt_x<<<total / 256, 256>>>(x);
    }
    {
        dim3 grid(NDIM / BN, MDIM / BM);
        k_gemm<<<grid, 256>>>(bias, out);
    }
}

// round 4
// speedup vs baseline: 1.0673x; 1.0673x over previous
#include <cuda_runtime.h>
#include <cuda_fp16.h>
#include <cstdint>

#define MDIM 4096
#define NDIM 4096
#define KDIM 4096

#define BM 128
#define BN 128
#define BK 64
#define STAGES 3
#define KT_ITERS (KDIM / BK)      // 64

#define A_STRIDE 72               // 64 + 8 pad (halfs)
#define B_STRIDE 136              // 128 + 8 pad (halfs)
#define A_TILE_H (BM * A_STRIDE)  // 9216 halfs
#define B_TILE_H (BK * B_STRIDE)  // 8704 halfs
#define SM_TOTAL ((STAGES * (A_TILE_H + B_TILE_H)) * 2)   // 107520 B

// Scratch (allocation-free rule: __device__ globals)
__device__ __half g_x16[(size_t)MDIM * KDIM];   // A [M][K]
__device__ __half g_w16[(size_t)KDIM * NDIM];   // W [K][N]

__device__ __forceinline__ uint32_t smem_u32(const void* p) {
    return (uint32_t)__cvta_generic_to_shared(p);
}

// ---------------------------------------------------------------------------
// Kernel 1: dequantize packed 4-bit -> fp16 W[k][n]
// packed[i, n] holds k = i*8 + j in nibble j (j = 0..7); group g = i/16
// ---------------------------------------------------------------------------
__global__ void k_dequant(const int* __restrict__ packed,
                          const float* __restrict__ scales,
                          const float* __restrict__ zeros) {
    int idx = blockIdx.x * blockDim.x + threadIdx.x;   // (K/8)*N = 2M
    int n = idx & (NDIM - 1);
    int i = idx >> 12;
    int g = i >> 4;
    float s = __ldg(&scales[g * NDIM + n]);
    float z = __ldg(&zeros[g * NDIM + n]);
    int p = __ldg(&packed[idx]);
#pragma unroll
    for (int j = 0; j < 8; j++) {
        int w = (p >> (4 * j)) & 15;
        g_w16[(size_t)(i * 8 + j) * NDIM + n] = __float2half(((float)w - z) * s);
    }
}

// ---------------------------------------------------------------------------
// Kernel 2: x fp32 -> fp16
// ---------------------------------------------------------------------------
__global__ void k_cvt_x(const float* __restrict__ x) {
    int idx = blockIdx.x * blockDim.x + threadIdx.x;   // 16M/4
    float4 v = ((const float4*)x)[idx];
    ((__half2*)g_x16)[idx * 2 + 0] = __floats2half2_rn(v.x, v.y);
    ((__half2*)g_x16)[idx * 2 + 1] = __floats2half2_rn(v.z, v.w);
}

// ---------------------------------------------------------------------------
// Kernel 3: fp16 GEMM (mma.sync), fp32 accumulate, + bias
// 128x128x64 tile, 256 threads (8 warps 4x2, warp tile 32x64),
// 3-stage cp.async pipeline, one barrier per K-tile.
// ---------------------------------------------------------------------------
#define LOAD_STAGE(KT_, SLOT_) do {                                           \
    int k0_ = (KT_) * BK;                                                     \
    __half* sA_ = As + (SLOT_) * A_TILE_H;                                    \
    __half* sB_ = Bs + (SLOT_) * B_TILE_H;                                    \
    _Pragma("unroll")                                                         \
    for (int j_ = 0; j_ < 4; j_++) {                                          \
        int c_ = tid + j_ * 256;                                              \
        int ar_ = c_ >> 3, ac_ = (c_ & 7) * 8;                                \
        const __half* gA_ = g_x16 + (size_t)(bm + ar_) * KDIM + k0_ + ac_;    \
        uint32_t soA_ = smem_u32(sA_ + ar_ * A_STRIDE + ac_);                 \
        asm volatile("cp.async.cg.shared.global [%0], [%1], 16;"              \
                     :: "r"(soA_), "l"(gA_) : "memory");                      \
        int br_ = c_ >> 4, bc_ = (c_ & 15) * 8;                               \
        const __half* gB_ = g_w16 + (size_t)(k0_ + br_) * NDIM + bn + bc_;    \
        uint32_t soB_ = smem_u32(sB_ + br_ * B_STRIDE + bc_);                 \
        asm volatile("cp.async.cg.shared.global [%0], [%1], 16;"              \
                     :: "r"(soB_), "l"(gB_) : "memory");                      \
    }                                                                         \
    asm volatile("cp.async.commit_group;" ::: "memory");                      \
} while (0)

__global__ void __launch_bounds__(256, 2)
k_gemm(const float* __restrict__ bias, float* __restrict__ C) {
    extern __shared__ __half smem[];
    __half* As = smem;
    __half* Bs = smem + STAGES * A_TILE_H;

    const int tid  = threadIdx.x;
    const int warp = tid >> 5;
    const int lane = tid & 31;
    const int wm = warp & 3;
    const int wn = warp >> 2;
    const int bm = blockIdx.y * BM;
    const int bn = blockIdx.x * BN;

    float acc[2][8][4];
#pragma unroll
    for (int mt = 0; mt < 2; mt++)
#pragma unroll
        for (int nt = 0; nt < 8; nt++)
#pragma unroll
            for (int r = 0; r < 4; r++) acc[mt][nt][r] = 0.0f;

    // prologue: stages 0, 1
    LOAD_STAGE(0, 0);
    LOAD_STAGE(1, 1);

    int slot = 0;        // slot of stage kt
    int nslot = 2;       // slot for stage kt+2
    for (int kt = 0; kt < KT_ITERS; kt++) {
        if (kt < KT_ITERS - 1)
            asm volatile("cp.async.wait_group 1;" ::: "memory");
        else
            asm volatile("cp.async.wait_group 0;" ::: "memory");
        __syncthreads();

        if (kt + 2 < KT_ITERS) LOAD_STAGE(kt + 2, nslot);

        const __half* sA = As + slot * A_TILE_H;
        const __half* sB = Bs + slot * B_TILE_H;

#pragma unroll
        for (int ks = 0; ks < 4; ks++) {          // 4 x k16 per BK=64
            int k0 = ks * 16;
            uint32_t a[2][4];
#pragma unroll
            for (int mt = 0; mt < 2; mt++) {
                int row = wm * 32 + mt * 16 + (lane & 15);
                int col = k0 + (lane >> 4) * 8;
                uint32_t addr = smem_u32(sA + row * A_STRIDE + col);
                asm volatile(
                    "ldmatrix.sync.aligned.m8n8.x4.shared.b16 {%0,%1,%2,%3}, [%4];"
                    : "=r"(a[mt][0]), "=r"(a[mt][1]), "=r"(a[mt][2]), "=r"(a[mt][3])
                    : "r"(addr));
            }
            uint32_t b[8][2];
#pragma unroll
            for (int nq = 0; nq < 4; nq++) {
                int row = k0 + (lane & 15);
                int col = wn * 64 + nq * 16 + (lane >> 4) * 8;
                uint32_t addr = smem_u32(sB + row * B_STRIDE + col);
                asm volatile(
                    "ldmatrix.sync.aligned.m8n8.x4.trans.shared.b16 {%0,%1,%2,%3}, [%4];"
                    : "=r"(b[nq * 2][0]), "=r"(b[nq * 2][1]),
                      "=r"(b[nq * 2 + 1][0]), "=r"(b[nq * 2 + 1][1])
                    : "r"(addr));
            }
#pragma unroll
            for (int mt = 0; mt < 2; mt++) {
#pragma unroll
                for (int nt = 0; nt < 8; nt++) {
                    asm volatile(
                        "mma.sync.aligned.m16n8k16.row.col.f32.f16.f16.f32 "
                        "{%0,%1,%2,%3}, {%4,%5,%6,%7}, {%8,%9}, {%0,%1,%2,%3};"
                        : "+f"(acc[mt][nt][0]), "+f"(acc[mt][nt][1]),
                          "+f"(acc[mt][nt][2]), "+f"(acc[mt][nt][3])
                        : "r"(a[mt][0]), "r"(a[mt][1]), "r"(a[mt][2]), "r"(a[mt][3]),
                          "r"(b[nt][0]), "r"(b[nt][1]));
                }
            }
        }

        slot = (slot == STAGES - 1) ? 0 : slot + 1;
        nslot = (nslot == STAGES - 1) ? 0 : nslot + 1;
    }

    // epilogue with bias
#pragma unroll
    for (int mt = 0; mt < 2; mt++) {
        int row0 = bm + wm * 32 + mt * 16 + (lane >> 2);
#pragma unroll
        for (int nt = 0; nt < 8; nt++) {
            int col = bn + wn * 64 + nt * 8 + (lane & 3) * 2;
            float b0 = __ldg(&bias[col]);
            float b1 = __ldg(&bias[col + 1]);
            float2 v0 = make_float2(acc[mt][nt][0] + b0, acc[mt][nt][1] + b1);
            float2 v1 = make_float2(acc[mt][nt][2] + b0, acc[mt][nt][3] + b1);
            *(float2*)&C[(size_t)row0 * NDIM + col] = v0;
            *(float2*)&C[(size_t)(row0 + 8) * NDIM + col] = v1;
        }
    }
}

// ---------------------------------------------------------------------------
// Launch: inputs: x, W_q_packed, scales, zeros, bias
// ---------------------------------------------------------------------------
extern "C" void kernel_launch(void* const* d_in, const int* in_sizes, int n_in,
                              void* d_out, int out_size) {
    const float* x      = (const float*)d_in[0];
    const int*   wq     = (const int*)d_in[1];
    const float* scales = (const float*)d_in[2];
    const float* zeros  = (const float*)d_in[3];
    const float* bias   = (const float*)d_in[4];
    float* out = (float*)d_out;

    {
        int total = (KDIM / 8) * NDIM;
        k_dequant<<<total / 256, 256>>>(wq, scales, zeros);
    }
    {
        int total = (MDIM * KDIM) / 4;
        k_cvt_x<<<total / 256, 256>>>(x);
    }
    {
        cudaFuncSetAttribute(k_gemm, cudaFuncAttributeMaxDynamicSharedMemorySize, SM_TOTAL);
        dim3 grid(NDIM / BN, MDIM / BM);
        k_gemm<<<grid, 256, SM_TOTAL>>>(bias, out);
    }
}